// round 16
// baseline (speedup 1.0000x reference)
#include <cuda_runtime.h>
#include <cuda_fp16.h>
#include <math.h>
#include <stdint.h>

#define B_    4
#define T_    1000
#define C_    1024
#define H_    16
#define D_    64
#define M_TOK (B_*T_)   // 4000
#define MPAD  4096

// Scratch (allocation-free device globals; zero-init -> pad rows are 0)
__device__ __half g_q[B_*H_*T_*D_];
__device__ __half g_k[B_*H_*T_*D_];
__device__ __half g_v[B_*H_*T_*D_];
__device__ __half g_xa[MPAD*C_];     // x, fp16
__device__ __half g_ya[MPAD*C_];     // attention out, fp16
__device__ __half g_wat[3*C_*C_];    // W_attn^T [3072][1024] fp16
__device__ __half g_wpt[C_*C_];      // W_proj^T [1024][1024] fp16
__device__ float  g_cos[T_*(D_/2)];
__device__ float  g_sin[T_*(D_/2)];

// ---------------------------------------------------------------------------
__device__ __forceinline__ void mma_f16(float c[4],
                                        const uint32_t a[4],
                                        const uint32_t b[2]) {
    asm volatile(
        "mma.sync.aligned.m16n8k16.row.col.f32.f16.f16.f32 "
        "{%0,%1,%2,%3}, {%4,%5,%6,%7}, {%8,%9}, {%0,%1,%2,%3};"
        : "+f"(c[0]), "+f"(c[1]), "+f"(c[2]), "+f"(c[3])
        : "r"(a[0]), "r"(a[1]), "r"(a[2]), "r"(a[3]),
          "r"(b[0]), "r"(b[1]));
}

__device__ __forceinline__ void ldsm_x4(uint32_t r[4], uint32_t smaddr) {
    asm volatile(
        "ldmatrix.sync.aligned.m8n8.x4.shared.b16 {%0,%1,%2,%3}, [%4];"
        : "=r"(r[0]), "=r"(r[1]), "=r"(r[2]), "=r"(r[3])
        : "r"(smaddr));
}

__device__ __forceinline__ void ldsm_x4_t(uint32_t r[4], uint32_t smaddr) {
    asm volatile(
        "ldmatrix.sync.aligned.m8n8.x4.trans.shared.b16 {%0,%1,%2,%3}, [%4];"
        : "=r"(r[0]), "=r"(r[1]), "=r"(r[2]), "=r"(r[3])
        : "r"(smaddr));
}

__device__ __forceinline__ void cp16(uint32_t smaddr, const void* gptr) {
    asm volatile("cp.async.cg.shared.global [%0], [%1], 16;"
                 :: "r"(smaddr), "l"(gptr));
}
__device__ __forceinline__ void cp_commit() {
    asm volatile("cp.async.commit_group;" ::: "memory");
}
__device__ __forceinline__ void cp_wait0() {
    asm volatile("cp.async.wait_group 0;" ::: "memory");
}

// ---------------------------------------------------------------------------
__global__ void rope_table_kernel() {
    int t = blockIdx.x;
    int i = threadIdx.x;
    float theta = (float)pow(10000.0, -(double)(2 * i) / 64.0);
    float ang = (float)t * theta;
    g_cos[t * 32 + i] = cosf(ang);
    g_sin[t * 32 + i] = sinf(ang);
}

__global__ void cvt_h_kernel(const float4* __restrict__ src,
                             uint2* __restrict__ dst, int n4) {
    int i = blockIdx.x * blockDim.x + threadIdx.x;
    if (i < n4) {
        float4 v = src[i];
        __half2 h0 = __floats2half2_rn(v.x, v.y);
        __half2 h1 = __floats2half2_rn(v.z, v.w);
        uint2 o;
        o.x = *(uint32_t*)&h0;
        o.y = *(uint32_t*)&h1;
        dst[i] = o;
    }
}

__global__ void transpose_h_kernel(const float* __restrict__ src,
                                   __half* __restrict__ dst,
                                   int K, int N) {
    __shared__ float tile[32][33];
    int n0 = blockIdx.x * 32, k0 = blockIdx.y * 32;
    int tx = threadIdx.x, ty = threadIdx.y;
#pragma unroll
    for (int j = 0; j < 32; j += 8)
        tile[ty + j][tx] = src[(size_t)(k0 + ty + j) * N + n0 + tx];
    __syncthreads();
#pragma unroll
    for (int j = 0; j < 32; j += 8)
        dst[(size_t)(n0 + ty + j) * K + k0 + tx] = __float2half(tile[tx][ty + j]);
}

// ---------------------------------------------------------------------------
// 128x128 fp16 GEMM (R15, proven): BK=64, cp.async, LDSM A+B.
// ---------------------------------------------------------------------------
#define BKH   64
#define GST   72
#define A_SZ  (128 * GST * 2)
#define STG   (2 * A_SZ)
#define GEMM_SMEM (2 * STG)

template<int MODE>
__global__ void __launch_bounds__(256, 2)
gemm_f16(const __half* __restrict__ A, const __half* __restrict__ Bt,
         float* __restrict__ Cout, int M, int N, int K)
{
    extern __shared__ __align__(16) uint8_t dsm[];
    const uint32_t smb = (uint32_t)__cvta_generic_to_shared(dsm);

    const int tid  = threadIdx.x;
    const int warp = tid >> 5;
    const int lane = tid & 31;
    const int g    = lane >> 2;
    const int tg   = lane & 3;
    const int wm   = warp >> 2;
    const int wn   = warp & 3;
    const int wmB  = wm * 64;
    const int wnB  = wn * 32;

    const int bm = blockIdx.y * 128;
    const int bn = blockIdx.x * 128;

    float acc[4][4][4];
#pragma unroll
    for (int mf = 0; mf < 4; mf++)
#pragma unroll
        for (int nf = 0; nf < 4; nf++)
#pragma unroll
            for (int i = 0; i < 4; i++) acc[mf][nf][i] = 0.f;

    const int rA  = lane & 15;
    const int cA  = (lane >> 4) * 8;
    const int rB  = (lane >> 4) * 8 + (lane & 7);
    const int cB  = ((lane >> 3) & 1) * 8;

    const int nchunk = K / BKH;

    auto issue = [&](int ch, int s) {
        const int k0 = ch * BKH;
        const uint32_t ab = smb + (uint32_t)(s * STG);
        const uint32_t bb = ab + A_SZ;
#pragma unroll
        for (int u = 0; u < 4; u++) {
            int i   = u * 256 + tid;
            int row = i >> 3;
            int q8  = (i & 7) * 8;
            cp16(ab + (uint32_t)((row * GST + q8) * 2),
                 A + (size_t)(bm + row) * K + k0 + q8);
            cp16(bb + (uint32_t)((row * GST + q8) * 2),
                 Bt + (size_t)(bn + row) * K + k0 + q8);
        }
        cp_commit();
    };

    issue(0, 0);
    cp_wait0();
    __syncthreads();

    for (int ch = 0; ch < nchunk; ch++) {
        const int cur = ch & 1;
        const bool have_next = (ch + 1 < nchunk);

        if (have_next) issue(ch + 1, cur ^ 1);

        const uint32_t ab = smb + (uint32_t)(cur * STG);
        const uint32_t bb = ab + A_SZ;

#pragma unroll
        for (int s = 0; s < 4; s++) {
            uint32_t afr[4][4];
#pragma unroll
            for (int mf = 0; mf < 4; mf++) {
                uint32_t addr = ab + (uint32_t)(
                    ((wmB + mf * 16 + rA) * GST + s * 16 + cA) * 2);
                ldsm_x4(afr[mf], addr);
            }
            uint32_t bfr[4][2];
#pragma unroll
            for (int nfb = 0; nfb < 2; nfb++) {
                uint32_t v4[4];
                uint32_t addr = bb + (uint32_t)(
                    ((wnB + nfb * 16 + rB) * GST + s * 16 + cB) * 2);
                ldsm_x4(v4, addr);
                bfr[2 * nfb][0]     = v4[0];
                bfr[2 * nfb][1]     = v4[1];
                bfr[2 * nfb + 1][0] = v4[2];
                bfr[2 * nfb + 1][1] = v4[3];
            }
#pragma unroll
            for (int mf = 0; mf < 4; mf++)
#pragma unroll
                for (int nf = 0; nf < 4; nf++)
                    mma_f16(acc[mf][nf], afr[mf], bfr[nf]);
        }

        if (have_next) {
            cp_wait0();
            __syncthreads();
        }
    }

    if (MODE == 1) {
#pragma unroll
        for (int mf = 0; mf < 4; mf++) {
#pragma unroll
            for (int half = 0; half < 2; half++) {
                int gr = bm + wmB + mf * 16 + g + half * 8;
                if (gr >= M) continue;
#pragma unroll
                for (int nf = 0; nf < 4; nf++) {
                    int c = bn + wnB + nf * 8 + tg * 2;
                    *(float2*)&Cout[(size_t)gr * N + c] =
                        make_float2(acc[mf][nf][2 * half], acc[mf][nf][2 * half + 1]);
                }
            }
        }
    } else {
        int cwarp = bn + wnB;
        int which = cwarp >> 10;
        int h     = (cwarp & 1023) >> 6;
#pragma unroll
        for (int mf = 0; mf < 4; mf++) {
#pragma unroll
            for (int half = 0; half < 2; half++) {
                int gr = bm + wmB + mf * 16 + g + half * 8;
                if (gr >= M) continue;
                int b = gr / T_;
                int t = gr - b * T_;
                size_t rowbase = ((size_t)(b * H_ + h) * T_ + t) * D_;
#pragma unroll
                for (int nf = 0; nf < 4; nf++) {
                    int dbase = (wnB + nf * 8 + tg * 2) & 63;
                    float x0 = acc[mf][nf][2 * half];
                    float x1 = acc[mf][nf][2 * half + 1];
                    if (which == 2) {
                        *(__half2*)&g_v[rowbase + dbase] = __floats2half2_rn(x0, x1);
                    } else {
                        int pi = dbase >> 1;
                        float ct = g_cos[t * 32 + pi];
                        float st = g_sin[t * 32 + pi];
                        __half* dst = (which == 0 ? g_q : g_k) + rowbase + dbase;
                        *(__half2*)dst = __floats2half2_rn(x0 * ct - x1 * st,
                                                           x1 * ct + x0 * st);
                    }
                }
            }
        }
    }
}

// ---------------------------------------------------------------------------
// fp16 flash attention, q-tile 128 (256 thr / 8 warps), kv-tile 64.
// Warp w owns q rows qt*128 + w*16 .. +15. K/V loaded once per 128 q rows
// (halves L2 traffic vs q-tile 64). Fully-masked warp-tiles skip compute.
// ---------------------------------------------------------------------------
#define KST 72

__global__ void __launch_bounds__(256) attn_f16_kernel() {
    const int qt = (int)gridDim.x - 1 - (int)blockIdx.x;  // heavy tiles first
    const int h  = blockIdx.y;
    const int b  = blockIdx.z;

    __shared__ __align__(16) __half SmQP[128 * KST];  // Q staging, then P tile
    __shared__ __align__(16) __half SmK[64 * KST];
    __shared__ __align__(16) __half SmV[64 * KST];

    const int tid  = threadIdx.x;
    const int warp = tid >> 5;
    const int lane = tid & 31;
    const int g    = lane >> 2;
    const int tg   = lane & 3;
    const int qw   = warp * 16;
    const int qbase = qt * 128;

    const size_t base = (size_t)(b * H_ + h) * T_ * D_;

    const uint32_t qp_sm = (uint32_t)__cvta_generic_to_shared(SmQP);
    const uint32_t kb_sm = (uint32_t)__cvta_generic_to_shared(SmK);
    const uint32_t vb_sm = (uint32_t)__cvta_generic_to_shared(SmV);

    // ---- stage Q tile (128 rows), extract Q^T B-fragments ----
#pragma unroll
    for (int u = 0; u < 4; u++) {
        int i   = u * 256 + tid;
        int row = i >> 3;
        int c8  = (i & 7) * 8;
        int grow = min(qbase + row, T_ - 1);
        *(uint4*)&SmQP[row * KST + c8] = *(const uint4*)&g_q[base + (size_t)grow * D_ + c8];
    }
    __syncthreads();

    uint32_t qb[4][2][2];
#pragma unroll
    for (int s = 0; s < 4; s++)
#pragma unroll
        for (int nf = 0; nf < 2; nf++) {
            const __half* qp = &SmQP[(qw + nf * 8 + g) * KST + s * 16 + 2 * tg];
            qb[s][nf][0] = *(const uint32_t*)qp;
            qb[s][nf][1] = *(const uint32_t*)(qp + 8);
        }
    __syncthreads();

    float Ofr[8][4];
#pragma unroll
    for (int nf = 0; nf < 8; nf++)
#pragma unroll
        for (int i = 0; i < 4; i++) Ofr[nf][i] = 0.f;
    float mrun[4] = {-1e30f, -1e30f, -1e30f, -1e30f};
    float lrun[4] = {0.f, 0.f, 0.f, 0.f};

    const int srcl = (g >> 1) & 3;
    const int nkt = 2 * qt + 2;

    for (int kt = 0; kt < nkt; kt++) {
        const int kb = kt * 64;

        // load K/V tiles (64 rows each, 256 threads -> 2 uint4 each)
#pragma unroll
        for (int u = 0; u < 2; u++) {
            int i   = u * 256 + tid;
            int row = i >> 3;
            int c8  = (i & 7) * 8;
            int grow = min(kb + row, T_ - 1);
            *(uint4*)&SmK[row * KST + c8] = *(const uint4*)&g_k[base + (size_t)grow * D_ + c8];
            *(uint4*)&SmV[row * KST + c8] = *(const uint4*)&g_v[base + (size_t)grow * D_ + c8];
        }
        __syncthreads();

        // warp-tile fully above diagonal? skip all compute
        const bool active = (kb <= qbase + qw + 15);
        if (active) {
            // ---- Phase A: S^T[kv][q] = K · Q^T ----
            float cS[4][2][4];
#pragma unroll
            for (int mf = 0; mf < 4; mf++)
#pragma unroll
                for (int nf = 0; nf < 2; nf++)
#pragma unroll
                    for (int i = 0; i < 4; i++) cS[mf][nf][i] = 0.f;

#pragma unroll
            for (int s = 0; s < 4; s++) {
#pragma unroll
                for (int mf = 0; mf < 4; mf++) {
                    uint32_t a[4];
                    uint32_t addr = kb_sm + (uint32_t)(
                        ((mf * 16 + (lane & 15)) * KST + (lane >> 4) * 8 + s * 16) * 2);
                    ldsm_x4(a, addr);
                    mma_f16(cS[mf][0], a, qb[s][0]);
                    mma_f16(cS[mf][1], a, qb[s][1]);
                }
            }

#pragma unroll
            for (int mf = 0; mf < 4; mf++)
#pragma unroll
                for (int nf = 0; nf < 2; nf++)
#pragma unroll
                    for (int i = 0; i < 4; i++) cS[mf][nf][i] *= 0.125f;

            // causal mask when this warp-tile intersects the diagonal
            if (kb + 63 > qbase + qw) {
#pragma unroll
                for (int mf = 0; mf < 4; mf++)
#pragma unroll
                    for (int nf = 0; nf < 2; nf++)
#pragma unroll
                        for (int i = 0; i < 4; i++) {
                            int kvg = kb + mf * 16 + g + (i >> 1) * 8;
                            int qg  = qbase + qw + nf * 8 + 2 * tg + (i & 1);
                            if (kvg > qg) cS[mf][nf][i] = -1e30f;
                        }
            }

            // ---- online softmax over q-columns ----
            float tmax[4];
#pragma unroll
            for (int nf = 0; nf < 2; nf++)
#pragma unroll
                for (int e = 0; e < 2; e++) {
                    float v = -1e30f;
#pragma unroll
                    for (int mf = 0; mf < 4; mf++)
                        v = fmaxf(v, fmaxf(cS[mf][nf][e], cS[mf][nf][2 + e]));
                    tmax[nf * 2 + e] = v;
                }
#pragma unroll
            for (int st = 0; st < 4; st++) {
                tmax[st] = fmaxf(tmax[st], __shfl_xor_sync(0xffffffffu, tmax[st], 4));
                tmax[st] = fmaxf(tmax[st], __shfl_xor_sync(0xffffffffu, tmax[st], 8));
                tmax[st] = fmaxf(tmax[st], __shfl_xor_sync(0xffffffffu, tmax[st], 16));
            }
            float fst[4];
#pragma unroll
            for (int st = 0; st < 4; st++) {
                float mnew = fmaxf(mrun[st], tmax[st]);
                fst[st] = __expf(mrun[st] - mnew);
                mrun[st] = mnew;
                lrun[st] *= fst[st];
            }

#pragma unroll
            for (int mf = 0; mf < 4; mf++)
#pragma unroll
                for (int nf = 0; nf < 2; nf++)
#pragma unroll
                    for (int i = 0; i < 4; i++) {
                        float p = __expf(cS[mf][nf][i] - mrun[nf * 2 + (i & 1)]);
                        cS[mf][nf][i] = p;
                        lrun[nf * 2 + (i & 1)] += p;
                    }

            // store P (fp16) into warp-private rows of SmQP
            __half* Ps = SmQP;
#pragma unroll
            for (int mf = 0; mf < 4; mf++)
#pragma unroll
                for (int nf = 0; nf < 2; nf++)
#pragma unroll
                    for (int i = 0; i < 4; i++) {
                        int qloc = qw + nf * 8 + 2 * tg + (i & 1);
                        int kv   = mf * 16 + g + (i >> 1) * 8;
                        Ps[qloc * KST + kv] = __float2half(cS[mf][nf][i]);
                    }
            __syncwarp();

            // rescale O
            {
                float f0 = __shfl_sync(0xffffffffu, fst[0], srcl);
                float f1 = __shfl_sync(0xffffffffu, fst[1], srcl);
                float f2 = __shfl_sync(0xffffffffu, fst[2], srcl);
                float f3 = __shfl_sync(0xffffffffu, fst[3], srcl);
                float fr0 = (g & 1) ? f1 : f0;
                float fr1 = (g & 1) ? f3 : f2;
#pragma unroll
                for (int nf = 0; nf < 8; nf++) {
                    Ofr[nf][0] *= fr0;
                    Ofr[nf][1] *= fr0;
                    Ofr[nf][2] *= fr1;
                    Ofr[nf][3] *= fr1;
                }
            }

            // ---- Phase B: O[q][d] += P · V ----
#pragma unroll
            for (int s = 0; s < 4; s++) {
                uint32_t aP[4];
                {
                    uint32_t addr = qp_sm + (uint32_t)(
                        ((qw + (lane & 15)) * KST + (lane >> 4) * 8 + s * 16) * 2);
                    ldsm_x4(aP, addr);
                }
#pragma unroll
                for (int np = 0; np < 4; np++) {
                    uint32_t v4[4];
                    uint32_t addr = vb_sm + (uint32_t)(
                        ((s * 16 + ((lane >> 3) & 1) * 8 + (lane & 7)) * KST
                         + np * 16 + (lane >> 4) * 8) * 2);
                    ldsm_x4_t(v4, addr);
                    uint32_t b0[2] = { v4[0], v4[1] };
                    uint32_t b1[2] = { v4[2], v4[3] };
                    mma_f16(Ofr[2 * np],     aP, b0);
                    mma_f16(Ofr[2 * np + 1], aP, b1);
                }
            }
        }
        __syncthreads();   // before next tile overwrites SmK/SmV
    }

    // reduce l across g-lanes
#pragma unroll
    for (int st = 0; st < 4; st++) {
        lrun[st] += __shfl_xor_sync(0xffffffffu, lrun[st], 4);
        lrun[st] += __shfl_xor_sync(0xffffffffu, lrun[st], 8);
        lrun[st] += __shfl_xor_sync(0xffffffffu, lrun[st], 16);
    }

    float l0 = __shfl_sync(0xffffffffu, lrun[0], srcl);
    float l1 = __shfl_sync(0xffffffffu, lrun[1], srcl);
    float l2 = __shfl_sync(0xffffffffu, lrun[2], srcl);
    float l3 = __shfl_sync(0xffffffffu, lrun[3], srcl);
    float lr0 = (g & 1) ? l1 : l0;
    float lr1 = (g & 1) ? l3 : l2;
    float inv0 = 1.f / lr0;
    float inv1 = 1.f / lr1;

    int qg0 = qbase + qw + g;
    int qg1 = qg0 + 8;
    if (qg0 < T_) {
        __half* yp = &g_ya[((size_t)(b * T_) + qg0) * C_ + h * D_];
#pragma unroll
        for (int nf = 0; nf < 8; nf++)
            *(__half2*)&yp[nf * 8 + 2 * tg] =
                __floats2half2_rn(Ofr[nf][0] * inv0, Ofr[nf][1] * inv0);
    }
    if (qg1 < T_) {
        __half* yp = &g_ya[((size_t)(b * T_) + qg1) * C_ + h * D_];
#pragma unroll
        for (int nf = 0; nf < 8; nf++)
            *(__half2*)&yp[nf * 8 + 2 * tg] =
                __floats2half2_rn(Ofr[nf][2] * inv1, Ofr[nf][3] * inv1);
    }
}

// ---------------------------------------------------------------------------
extern "C" void kernel_launch(void* const* d_in, const int* in_sizes, int n_in,
                              void* d_out, int out_size)
{
    const float* x      = (const float*)d_in[0];
    const float* W_attn = (const float*)d_in[2];
    const float* W_proj = (const float*)d_in[3];
    float* out = (float*)d_out;

    __half* xa;  cudaGetSymbolAddress((void**)&xa,  g_xa);
    __half* wat; cudaGetSymbolAddress((void**)&wat, g_wat);
    __half* wpt; cudaGetSymbolAddress((void**)&wpt, g_wpt);
    __half* ya;  cudaGetSymbolAddress((void**)&ya,  g_ya);

    cudaFuncSetAttribute(gemm_f16<0>, cudaFuncAttributeMaxDynamicSharedMemorySize, GEMM_SMEM);
    cudaFuncSetAttribute(gemm_f16<1>, cudaFuncAttributeMaxDynamicSharedMemorySize, GEMM_SMEM);

    rope_table_kernel<<<T_, 32>>>();

    cvt_h_kernel<<<(M_TOK*C_/4 + 255)/256, 256>>>((const float4*)x, (uint2*)xa, M_TOK*C_/4);
    transpose_h_kernel<<<dim3(3*C_/32, C_/32), dim3(32, 8)>>>(W_attn, wat, C_, 3*C_);
    transpose_h_kernel<<<dim3(C_/32,   C_/32), dim3(32, 8)>>>(W_proj, wpt, C_, C_);

    dim3 g_qkv(3072 / 128, MPAD / 128);            // 24 x 32
    gemm_f16<0><<<g_qkv, 256, GEMM_SMEM>>>(xa, wat, nullptr, M_TOK, 3072, 1024);

    dim3 g_attn((T_ + 127) / 128, H_, B_);         // 8 x 16 x 4
    attn_f16_kernel<<<g_attn, 256>>>();

    dim3 g_proj(1024 / 128, MPAD / 128);           // 8 x 32
    gemm_f16<1><<<g_proj, 256, GEMM_SMEM>>>(ya, wpt, out, M_TOK, 1024, 1024);
}